// round 13
// baseline (speedup 1.0000x reference)
#include <cuda_runtime.h>
#include <cuda_fp16.h>

// ---------------------------------------------------------------------------
// LapImage: fused 4-level trilinear grid_sample (align_corners=True)
// Round 13 (= Round 12 re-bench; R12 was an infra double-fail, precedent R3->R4):
//   * evict-first (__ldcs/__stcs) on ALL streaming point data so the 44.6MB
//     packed volumes stay L2-resident through sample
//   * scan2 kernel removed: scan1 thread 511 grabs its chunk base via a
//     global atomic cursor (bin regions stay disjoint+exact; output identical)
// Pipeline: zero -> repack_hist -> scan1(+atomic base) -> permute -> sample
//           -> unpermute        (6 launches)
// Sample/unpermute are 1 point/thread (R11 disproved 2 pts/thread).
// ---------------------------------------------------------------------------

#define NPTS   (4 * 96 * 96 * 96)   // 3,538,944
#define PLANE  (96 * 96 * 96)       // 884,736
#define NVOX   2785280              // 32768 + 131072 + 524288 + 2097152
#define NBINS  262144               // 32 z * 256 y * 32 x-lines (lvl3)
#define NBLK   512

__device__ uint4    g_vol[NVOX];      // 44.6 MB pair-packed fp16 volumes (x-innermost)
__device__ unsigned g_hist[NBINS];
__device__ unsigned g_cnt[NBINS];     // permute-time per-bin counters
__device__ unsigned g_off1[NBINS];    // exclusive scan within 512-chunk
__device__ unsigned g_off2[NBLK];     // chunk base offsets (atomic-assigned)
__device__ unsigned g_cursor;         // global chunk-base cursor
__device__ uint4    g_sorted[NPTS];   // {gx,gy,gz,p} -> overwritten with {r,g,b,-}
__device__ unsigned g_inv[NPTS];      // original index p -> sorted position

// ---------------- spatial key: lvl3 cache-line granularity -----------------
__device__ __forceinline__ int point_key(float gx, float gy, float gz) {
    int z0 = min((int)((gz + 1.0f) * 15.5f), 30);
    int y3 = min((int)((gy + 1.0f) * 127.5f), 254);
    int x3 = min((int)((gx + 1.0f) * 127.5f), 254);
    return (z0 * 256 + y3) * 32 + (x3 >> 3);   // 8 pair-entries = 128B line
}

__global__ __launch_bounds__(256)
void zero_kernel() {
    int i = blockIdx.x * blockDim.x + threadIdx.x;
    if (i < NBINS) { g_hist[i] = 0u; g_cnt[i] = 0u; }
    if (i == 0) g_cursor = 0u;
}

// ---------------- fused repack (i < NVOX) + histogram (i < NPTS) -----------
__global__ __launch_bounds__(256)
void repack_hist_kernel(const float* __restrict__ coords,
                        const float* __restrict__ i0, const float* __restrict__ i1,
                        const float* __restrict__ i2, const float* __restrict__ i3) {
    int i = blockIdx.x * blockDim.x + threadIdx.x;

    if (i < NVOX) {
        const float* __restrict__ src;
        int n, base;
        if (i < 32768)        { src = i0; n = 32768;   base = 0;      }
        else if (i < 163840)  { src = i1; n = 131072;  base = 32768;  }
        else if (i < 688128)  { src = i2; n = 524288;  base = 163840; }
        else                  { src = i3; n = 2097152; base = 688128; }

        int li = i - base;
        int j  = min(li + 1, n - 1);   // x+1 neighbor; row-crossing entry never sampled

        __half2 p0 = __halves2half2(__float2half_rn(__ldcs(src + li)),
                                    __float2half_rn(__ldcs(src + n + li)));
        __half2 p1 = __halves2half2(__float2half_rn(__ldcs(src + 2 * n + li)),
                                    __float2half_rn(__ldcs(src + j)));
        __half2 p2 = __halves2half2(__float2half_rn(__ldcs(src + n + j)),
                                    __float2half_rn(__ldcs(src + 2 * n + j)));
        uint4 v;
        v.x = *(unsigned int*)&p0;
        v.y = *(unsigned int*)&p1;
        v.z = *(unsigned int*)&p2;
        v.w = 0u;
        g_vol[i] = v;                  // default policy: keep resident in L2
    }

    if (i < NPTS) {
        float gx = __ldcs(coords + 3 * i);
        float gy = __ldcs(coords + 3 * i + 1);
        float gz = __ldcs(coords + 3 * i + 2);
        atomicAdd(&g_hist[point_key(gx, gy, gz)], 1u);
    }
}

// scan1: exclusive scan within each 512-chunk; chunk base via atomic cursor
__global__ __launch_bounds__(512)
void scan1_kernel() {
    __shared__ unsigned s[512];
    int t   = threadIdx.x;
    int idx = blockIdx.x * 512 + t;
    unsigned v = g_hist[idx];
    s[t] = v;
    __syncthreads();
#pragma unroll
    for (int d = 1; d < 512; d <<= 1) {
        unsigned add = (t >= d) ? s[t - d] : 0u;
        __syncthreads();
        s[t] += add;
        __syncthreads();
    }
    g_off1[idx] = s[t] - v;
    if (t == 511) g_off2[blockIdx.x] = atomicAdd(&g_cursor, s[t]);
}

__global__ __launch_bounds__(256)
void permute_kernel(const float* __restrict__ coords) {
    int p = blockIdx.x * blockDim.x + threadIdx.x;
    if (p >= NPTS) return;
    float gx = __ldcs(coords + 3 * p);
    float gy = __ldcs(coords + 3 * p + 1);
    float gz = __ldcs(coords + 3 * p + 2);
    int k = point_key(gx, gy, gz);
    unsigned rank = atomicAdd(&g_cnt[k], 1u);
    unsigned pos  = g_off1[k] + g_off2[k >> 9] + rank;
    uint4 r;
    r.x = __float_as_uint(gx);
    r.y = __float_as_uint(gy);
    r.z = __float_as_uint(gz);
    r.w = (unsigned)p;
    __stcs(&g_sorted[pos], r);
    __stcs(&g_inv[p], pos);
}

// ---------------- sampling over sorted points (coalesced in-place output) --
__device__ __forceinline__ void acc_pair(uint4 q, float w, float wx0, float wx1,
                                         float& ax, float& ay, float& az) {
    float2 f0 = __half22float2(*(__half2*)&q.x);   // c0(x0), c1(x0)
    float2 f1 = __half22float2(*(__half2*)&q.y);   // c2(x0), c0(x1)
    float2 f2 = __half22float2(*(__half2*)&q.z);   // c1(x1), c2(x1)
    ax = fmaf(w, fmaf(f0.x, wx0, f1.y * wx1), ax);
    ay = fmaf(w, fmaf(f0.y, wx0, f2.x * wx1), ay);
    az = fmaf(w, fmaf(f1.x, wx0, f2.y * wx1), az);
}

__global__ __launch_bounds__(256)
void sample_kernel() {
    int i = blockIdx.x * blockDim.x + threadIdx.x;
    if (i >= NPTS) return;

    uint4 rec = __ldcs(&g_sorted[i]);
    float gx = __uint_as_float(rec.x);
    float gy = __uint_as_float(rec.y);
    float gz = __uint_as_float(rec.z);

    float iz  = (gz + 1.0f) * 15.5f;
    float z0f = floorf(iz);
    float wz1 = iz - z0f;
    float wz0 = 1.0f - wz1;
    int   z0  = min((int)z0f, 30);

    float ax = 0.0f, ay = 0.0f, az = 0.0f;
    const int offs[4] = {0, 32768, 163840, 688128};

#pragma unroll
    for (int lvl = 0; lvl < 4; ++lvl) {
        const int   HW = 32 << lvl;
        const float sc = 0.5f * (float)(HW - 1);
        const uint4* __restrict__ vol = g_vol + offs[lvl];

        float ix  = (gx + 1.0f) * sc;
        float iy  = (gy + 1.0f) * sc;
        float x0f = floorf(ix);
        float y0f = floorf(iy);
        float wx1 = ix - x0f, wx0 = 1.0f - wx1;
        float wy1 = iy - y0f, wy0 = 1.0f - wy1;
        int x0 = min((int)x0f, HW - 2);
        int y0 = min((int)y0f, HW - 2);
        int y1 = y0 + 1;

        int r00 = (z0 * HW + y0) * HW + x0;
        int r01 = (z0 * HW + y1) * HW + x0;
        int r10 = r00 + HW * HW;
        int r11 = r01 + HW * HW;

        uint4 q00 = __ldg(vol + r00);   // keep resident
        uint4 q01 = __ldg(vol + r01);
        uint4 q10 = __ldg(vol + r10);
        uint4 q11 = __ldg(vol + r11);

        acc_pair(q00, wz0 * wy0, wx0, wx1, ax, ay, az);
        acc_pair(q01, wz0 * wy1, wx0, wx1, ax, ay, az);
        acc_pair(q10, wz1 * wy0, wx0, wx1, ax, ay, az);
        acc_pair(q11, wz1 * wy1, wx0, wx1, ax, ay, az);
    }

    uint4 res;                      // overwrite record with result (coalesced)
    res.x = __float_as_uint(ax);
    res.y = __float_as_uint(ay);
    res.z = __float_as_uint(az);
    res.w = 0u;
    __stcs(&g_sorted[i], res);
}

// ---------------- gather results back to [B,3,96^3] ------------------------
__global__ __launch_bounds__(256)
void unpermute_kernel(float* __restrict__ out) {
    int p = blockIdx.x * blockDim.x + threadIdx.x;
    if (p >= NPTS) return;
    unsigned pos = __ldcs(&g_inv[p]);     // coalesced
    uint4 r = __ldcs(&g_sorted[pos]);     // one scattered 16B gather
    int b  = p / PLANE;
    int pl = p - b * PLANE;
    float* o = out + (size_t)b * (3 * PLANE) + pl;
    __stcs(o,             __uint_as_float(r.x));
    __stcs(o + PLANE,     __uint_as_float(r.y));
    __stcs(o + 2 * PLANE, __uint_as_float(r.z));
}

extern "C" void kernel_launch(void* const* d_in, const int* in_sizes, int n_in,
                              void* d_out, int out_size) {
    const float* coords = (const float*)d_in[0];
    const float* img0   = (const float*)d_in[1];
    const float* img1   = (const float*)d_in[2];
    const float* img2   = (const float*)d_in[3];
    const float* img3   = (const float*)d_in[4];
    float* out = (float*)d_out;

    zero_kernel<<<NBINS / 256, 256>>>();
    repack_hist_kernel<<<(NPTS + 255) / 256, 256>>>(coords, img0, img1, img2, img3);
    scan1_kernel<<<NBLK, 512>>>();
    permute_kernel<<<NPTS / 256, 256>>>(coords);
    sample_kernel<<<NPTS / 256, 256>>>();
    unpermute_kernel<<<NPTS / 256, 256>>>(out);
}

// round 14
// speedup vs baseline: 1.1247x; 1.1247x over previous
#include <cuda_runtime.h>
#include <cuda_fp16.h>

// ---------------------------------------------------------------------------
// LapImage: fused 4-level trilinear grid_sample (align_corners=True)
// Round 14 = R9 base (198.7us) with:
//   * ALL cache hints reverted (R13 proved __ldcs/__stcs cost ~18us)
//   * scan2 stays deleted (atomic chunk-base cursor in scan1)
//   * permute: 4 points/thread, 3x float4 coord loads, 4 independent
//     atomic->store chains (permute measured latency-bound: 76us @ 6.5% issue)
// Pipeline: zero -> repack_hist -> scan1(+atomic base) -> permute4 -> sample
//           -> unpermute        (6 launches)
// ---------------------------------------------------------------------------

#define NPTS   (4 * 96 * 96 * 96)   // 3,538,944  (divisible by 4)
#define PLANE  (96 * 96 * 96)       // 884,736
#define NVOX   2785280              // 32768 + 131072 + 524288 + 2097152
#define NBINS  262144               // 32 z * 256 y * 32 x-lines (lvl3)
#define NBLK   512

__device__ uint4    g_vol[NVOX];      // 44.6 MB pair-packed fp16 volumes (x-innermost)
__device__ unsigned g_hist[NBINS];
__device__ unsigned g_cnt[NBINS];     // permute-time per-bin counters
__device__ unsigned g_off1[NBINS];    // exclusive scan within 512-chunk
__device__ unsigned g_off2[NBLK];     // chunk base offsets (atomic-assigned)
__device__ unsigned g_cursor;         // global chunk-base cursor
__device__ uint4    g_sorted[NPTS];   // {gx,gy,gz,p} -> overwritten with {r,g,b,-}
__device__ unsigned g_inv[NPTS];      // original index p -> sorted position

// ---------------- spatial key: lvl3 cache-line granularity -----------------
__device__ __forceinline__ int point_key(float gx, float gy, float gz) {
    int z0 = min((int)((gz + 1.0f) * 15.5f), 30);
    int y3 = min((int)((gy + 1.0f) * 127.5f), 254);
    int x3 = min((int)((gx + 1.0f) * 127.5f), 254);
    return (z0 * 256 + y3) * 32 + (x3 >> 3);   // 8 pair-entries = 128B line
}

__global__ __launch_bounds__(256)
void zero_kernel() {
    int i = blockIdx.x * blockDim.x + threadIdx.x;
    if (i < NBINS) { g_hist[i] = 0u; g_cnt[i] = 0u; }
    if (i == 0) g_cursor = 0u;
}

// ---------------- fused repack (i < NVOX) + histogram (i < NPTS) -----------
__global__ __launch_bounds__(256)
void repack_hist_kernel(const float* __restrict__ coords,
                        const float* __restrict__ i0, const float* __restrict__ i1,
                        const float* __restrict__ i2, const float* __restrict__ i3) {
    int i = blockIdx.x * blockDim.x + threadIdx.x;

    if (i < NVOX) {
        const float* __restrict__ src;
        int n, base;
        if (i < 32768)        { src = i0; n = 32768;   base = 0;      }
        else if (i < 163840)  { src = i1; n = 131072;  base = 32768;  }
        else if (i < 688128)  { src = i2; n = 524288;  base = 163840; }
        else                  { src = i3; n = 2097152; base = 688128; }

        int li = i - base;
        int j  = min(li + 1, n - 1);   // x+1 neighbor; row-crossing entry never sampled

        __half2 p0 = __halves2half2(__float2half_rn(src[li]),         __float2half_rn(src[n + li]));
        __half2 p1 = __halves2half2(__float2half_rn(src[2 * n + li]), __float2half_rn(src[j]));
        __half2 p2 = __halves2half2(__float2half_rn(src[n + j]),      __float2half_rn(src[2 * n + j]));
        uint4 v;
        v.x = *(unsigned int*)&p0;
        v.y = *(unsigned int*)&p1;
        v.z = *(unsigned int*)&p2;
        v.w = 0u;
        g_vol[i] = v;
    }

    if (i < NPTS) {
        atomicAdd(&g_hist[point_key(coords[3 * i], coords[3 * i + 1], coords[3 * i + 2])], 1u);
    }
}

// scan1: exclusive scan within each 512-chunk; chunk base via atomic cursor
__global__ __launch_bounds__(512)
void scan1_kernel() {
    __shared__ unsigned s[512];
    int t   = threadIdx.x;
    int idx = blockIdx.x * 512 + t;
    unsigned v = g_hist[idx];
    s[t] = v;
    __syncthreads();
#pragma unroll
    for (int d = 1; d < 512; d <<= 1) {
        unsigned add = (t >= d) ? s[t - d] : 0u;
        __syncthreads();
        s[t] += add;
        __syncthreads();
    }
    g_off1[idx] = s[t] - v;
    if (t == 511) g_off2[blockIdx.x] = atomicAdd(&g_cursor, s[t]);
}

// ---------------- permute: 4 points per thread (MLP on atomics) ------------
__global__ __launch_bounds__(256)
void permute_kernel(const float* __restrict__ coords) {
    int t = blockIdx.x * blockDim.x + threadIdx.x;
    int p = 4 * t;
    if (p >= NPTS) return;

    // 12 floats = 4 points, three coalesced 16B loads (48t bytes -> aligned)
    const float4* __restrict__ c4 = (const float4*)(coords + 3 * p);
    float4 A = c4[0];
    float4 B = c4[1];
    float4 C = c4[2];

    float gx[4] = {A.x, A.w, B.z, C.y};
    float gy[4] = {A.y, B.x, B.w, C.z};
    float gz[4] = {A.z, B.y, C.x, C.w};

    unsigned posv[4];
#pragma unroll
    for (int j = 0; j < 4; ++j) {
        int k = point_key(gx[j], gy[j], gz[j]);
        unsigned rank = atomicAdd(&g_cnt[k], 1u);      // 4 independent chains
        unsigned pos  = g_off1[k] + g_off2[k >> 9] + rank;
        uint4 r;
        r.x = __float_as_uint(gx[j]);
        r.y = __float_as_uint(gy[j]);
        r.z = __float_as_uint(gz[j]);
        r.w = (unsigned)(p + j);
        g_sorted[pos] = r;
        posv[j] = pos;
    }
    *(uint4*)&g_inv[p] = make_uint4(posv[0], posv[1], posv[2], posv[3]);
}

// ---------------- sampling over sorted points (coalesced in-place output) --
__device__ __forceinline__ void acc_pair(uint4 q, float w, float wx0, float wx1,
                                         float& ax, float& ay, float& az) {
    float2 f0 = __half22float2(*(__half2*)&q.x);   // c0(x0), c1(x0)
    float2 f1 = __half22float2(*(__half2*)&q.y);   // c2(x0), c0(x1)
    float2 f2 = __half22float2(*(__half2*)&q.z);   // c1(x1), c2(x1)
    ax = fmaf(w, fmaf(f0.x, wx0, f1.y * wx1), ax);
    ay = fmaf(w, fmaf(f0.y, wx0, f2.x * wx1), ay);
    az = fmaf(w, fmaf(f1.x, wx0, f2.y * wx1), az);
}

__global__ __launch_bounds__(256)
void sample_kernel() {
    int i = blockIdx.x * blockDim.x + threadIdx.x;
    if (i >= NPTS) return;

    uint4 rec = g_sorted[i];
    float gx = __uint_as_float(rec.x);
    float gy = __uint_as_float(rec.y);
    float gz = __uint_as_float(rec.z);

    float iz  = (gz + 1.0f) * 15.5f;
    float z0f = floorf(iz);
    float wz1 = iz - z0f;
    float wz0 = 1.0f - wz1;
    int   z0  = min((int)z0f, 30);

    float ax = 0.0f, ay = 0.0f, az = 0.0f;
    const int offs[4] = {0, 32768, 163840, 688128};

#pragma unroll
    for (int lvl = 0; lvl < 4; ++lvl) {
        const int   HW = 32 << lvl;
        const float sc = 0.5f * (float)(HW - 1);
        const uint4* __restrict__ vol = g_vol + offs[lvl];

        float ix  = (gx + 1.0f) * sc;
        float iy  = (gy + 1.0f) * sc;
        float x0f = floorf(ix);
        float y0f = floorf(iy);
        float wx1 = ix - x0f, wx0 = 1.0f - wx1;
        float wy1 = iy - y0f, wy0 = 1.0f - wy1;
        int x0 = min((int)x0f, HW - 2);
        int y0 = min((int)y0f, HW - 2);
        int y1 = y0 + 1;

        int r00 = (z0 * HW + y0) * HW + x0;
        int r01 = (z0 * HW + y1) * HW + x0;
        int r10 = r00 + HW * HW;
        int r11 = r01 + HW * HW;

        uint4 q00 = __ldg(vol + r00);
        uint4 q01 = __ldg(vol + r01);
        uint4 q10 = __ldg(vol + r10);
        uint4 q11 = __ldg(vol + r11);

        acc_pair(q00, wz0 * wy0, wx0, wx1, ax, ay, az);
        acc_pair(q01, wz0 * wy1, wx0, wx1, ax, ay, az);
        acc_pair(q10, wz1 * wy0, wx0, wx1, ax, ay, az);
        acc_pair(q11, wz1 * wy1, wx0, wx1, ax, ay, az);
    }

    uint4 res;                      // overwrite record with result (coalesced)
    res.x = __float_as_uint(ax);
    res.y = __float_as_uint(ay);
    res.z = __float_as_uint(az);
    res.w = 0u;
    g_sorted[i] = res;
}

// ---------------- gather results back to [B,3,96^3] ------------------------
__global__ __launch_bounds__(256)
void unpermute_kernel(float* __restrict__ out) {
    int p = blockIdx.x * blockDim.x + threadIdx.x;
    if (p >= NPTS) return;
    unsigned pos = g_inv[p];              // coalesced
    uint4 r = __ldg(&g_sorted[pos]);      // one scattered 16B gather (L2-resident)
    int b  = p / PLANE;
    int pl = p - b * PLANE;
    float* o = out + (size_t)b * (3 * PLANE) + pl;
    o[0]         = __uint_as_float(r.x);
    o[PLANE]     = __uint_as_float(r.y);
    o[2 * PLANE] = __uint_as_float(r.z);
}

extern "C" void kernel_launch(void* const* d_in, const int* in_sizes, int n_in,
                              void* d_out, int out_size) {
    const float* coords = (const float*)d_in[0];
    const float* img0   = (const float*)d_in[1];
    const float* img1   = (const float*)d_in[2];
    const float* img2   = (const float*)d_in[3];
    const float* img3   = (const float*)d_in[4];
    float* out = (float*)d_out;

    zero_kernel<<<NBINS / 256, 256>>>();
    repack_hist_kernel<<<(NPTS + 255) / 256, 256>>>(coords, img0, img1, img2, img3);
    scan1_kernel<<<NBLK, 512>>>();
    permute_kernel<<<NPTS / 4 / 256, 256>>>(coords);
    sample_kernel<<<NPTS / 256, 256>>>();
    unpermute_kernel<<<NPTS / 256, 256>>>(out);
}